// round 13
// baseline (speedup 1.0000x reference)
#include <cuda_runtime.h>
#include <cuda_fp16.h>
#include <cstdint>

// ---------------------------------------------------------------------------
// SelfAttention: out = softmax((x@Wq^T)(x@Wk^T)^T / sqrt(D)) @ (x@Wv^T)
// B=4, S=4096, D=1024.  fp16 tensor GEMMs (m16n8k16, fp32 accum).
// R13: word-interleaved smem layout -> fragment loads become LDS.64
// (12 wide loads vs 24 scalar per warp-k16).  Interleave built during
// LDG (uint2 pairs -> register interleave -> STS.128).  Proven instruction
// classes only (no cp.async / ldmatrix).  Tile/structure = R9 (best: 1355us).
// Layout: logical word j of each 8-word k-group stored at phys (j%4)*2+j/4;
// fragment pair (tg, tg+4) -> phys (2tg, 2tg+1) = one LDS.64.  PAD=40 words.
// ---------------------------------------------------------------------------

#define BM 128
#define BN 128
#define BKH 64   // k halves per tile = 32 words = 4 k16 groups
#define PAD 40   // smem row stride in words (160 B): conflict-free LDS.64/STS.128

static const int BATCH = 4;
static const int SEQ   = 4096;
static const int DIM   = 1024;

// Scratch (device globals: allocation-free rule)
__device__ __half g_Xh[4LL * 4096 * 1024];
__device__ __half g_Wh[3LL * 1024 * 1024];
__device__ __half g_Q [4LL * 4096 * 1024];
__device__ __half g_K [4LL * 4096 * 1024];
__device__ __half g_Vt[4LL * 1024 * 4096];   // per batch: [D][S]
__device__ float  g_S [4LL * 4096 * 4096];
__device__ __half g_P [4LL * 4096 * 4096];

__device__ __forceinline__ void mma_f16(float c[4],
                                        uint32_t a0, uint32_t a1, uint32_t a2, uint32_t a3,
                                        uint32_t b0, uint32_t b1) {
    asm volatile(
        "mma.sync.aligned.m16n8k16.row.col.f32.f16.f16.f32 "
        "{%0,%1,%2,%3}, {%4,%5,%6,%7}, {%8,%9}, {%0,%1,%2,%3};\n"
        : "+f"(c[0]), "+f"(c[1]), "+f"(c[2]), "+f"(c[3])
        : "r"(a0), "r"(a1), "r"(a2), "r"(a3), "r"(b0), "r"(b1));
}

// C[M,N] = alpha * A[M,K] @ B[N,K]^T  (fp16 in, fp32 accum; B stored N-major)
// OUT_HALF: C is __half else float.  Batched via blockIdx.z.
template <bool OUT_HALF>
__global__ __launch_bounds__(256, 1)
void gemm_h(const __half* __restrict__ A, const __half* __restrict__ B,
            void* __restrict__ Cv,
            int M, int N, int K, int lda, int ldb, int ldc,
            long long sA, long long sB, long long sC, float alpha)
{
    extern __shared__ uint32_t smem[];
    uint32_t* AsBase = smem;                   // [2][BM][PAD] words
    uint32_t* BsBase = smem + 2 * BM * PAD;    // [2][BN][PAD] words

    A += (long long)blockIdx.z * sA;
    B += (long long)blockIdx.z * sB;

    const int m0 = blockIdx.y * BM;
    const int n0 = blockIdx.x * BN;

    const int tid  = threadIdx.x;
    const int lane = tid & 31;
    const int wid  = tid >> 5;
    const int wm   = wid & 1;   // warp row (0..1), 64 rows each
    const int wn   = wid >> 1;  // warp col (0..3), 32 cols each
    const int g    = lane >> 2; // 0..7
    const int tg   = lane & 3;  // 0..3

    // staging: thread -> (row lrow+32i, 16B phys chunk q)
    const int lrow = tid >> 3;        // 0..31
    const int q    = tid & 7;         // phys chunk: kk = q>>1, p = q&1
    const int goff = 16 * (q >> 1) + 4 * (q & 1);  // halves: first uint2
    const int soff = 4 * q;                        // words: phys chunk base

    uint2 a1[4], a2[4], b1[4], b2[4];

    auto ldg_tile = [&](int k0) {
        #pragma unroll
        for (int i = 0; i < 4; i++) {
            int r = lrow + 32 * i;
            const __half* pa = &A[(long long)(m0 + r) * lda + k0 + goff];
            const __half* pb = &B[(long long)(n0 + r) * ldb + k0 + goff];
            a1[i] = *reinterpret_cast<const uint2*>(pa);
            a2[i] = *reinterpret_cast<const uint2*>(pa + 8);
            b1[i] = *reinterpret_cast<const uint2*>(pb);
            b2[i] = *reinterpret_cast<const uint2*>(pb + 8);
        }
    };
    auto sts_tile = [&](int st) {
        uint32_t* as = AsBase + st * BM * PAD;
        uint32_t* bs = BsBase + st * BN * PAD;
        #pragma unroll
        for (int i = 0; i < 4; i++) {
            int r = lrow + 32 * i;
            // interleave: phys chunk = {w, w+4, w+1, w+5} logical
            uint4 va = make_uint4(a1[i].x, a2[i].x, a1[i].y, a2[i].y);
            uint4 vb = make_uint4(b1[i].x, b2[i].x, b1[i].y, b2[i].y);
            *reinterpret_cast<uint4*>(&as[r * PAD + soff]) = va;
            *reinterpret_cast<uint4*>(&bs[r * PAD + soff]) = vb;
        }
    };

    float acc[4][4][4];
    #pragma unroll
    for (int mi = 0; mi < 4; mi++)
        #pragma unroll
        for (int ni = 0; ni < 4; ni++)
            #pragma unroll
            for (int j = 0; j < 4; j++) acc[mi][ni][j] = 0.0f;

    ldg_tile(0);
    sts_tile(0);
    __syncthreads();

    const int ntiles = K / BKH;
    for (int kt = 0; kt < ntiles; kt++) {
        const int st = kt & 1;
        if (kt + 1 < ntiles) ldg_tile((kt + 1) * BKH);

        const uint32_t* as = AsBase + st * BM * PAD;
        const uint32_t* bs = BsBase + st * BN * PAD;

        #pragma unroll
        for (int kk = 0; kk < 4; kk++) {       // four k16 steps
            const int kb = kk * 8;             // phys word offset of k-group
            // fragment loads: LDS.64 pairs
            uint2 afA[4], afB[4], bfp[4];
            #pragma unroll
            for (int mi = 0; mi < 4; mi++) {
                int row = wm * 64 + mi * 16 + g;
                afA[mi] = *reinterpret_cast<const uint2*>(&as[row * PAD + kb + 2 * tg]);        // (a0,a2)
                afB[mi] = *reinterpret_cast<const uint2*>(&as[(row + 8) * PAD + kb + 2 * tg]);  // (a1,a3)
            }
            #pragma unroll
            for (int ni = 0; ni < 4; ni++) {
                int col = wn * 32 + ni * 8 + g;
                bfp[ni] = *reinterpret_cast<const uint2*>(&bs[col * PAD + kb + 2 * tg]);        // (b0,b1)
            }
            #pragma unroll
            for (int mi = 0; mi < 4; mi++)
                #pragma unroll
                for (int ni = 0; ni < 4; ni++)
                    mma_f16(acc[mi][ni], afA[mi].x, afB[mi].x, afA[mi].y, afB[mi].y,
                            bfp[ni].x, bfp[ni].y);
        }

        if (kt + 1 < ntiles) sts_tile((kt + 1) & 1);
        __syncthreads();
    }

    // epilogue: c0:(g,2tg) c1:(g,2tg+1) c2:(g+8,2tg) c3:(g+8,2tg+1)
    #pragma unroll
    for (int mi = 0; mi < 4; mi++) {
        #pragma unroll
        for (int ni = 0; ni < 4; ni++) {
            int row = m0 + wm * 64 + mi * 16 + g;
            int col = n0 + wn * 32 + ni * 8 + 2 * tg;
            float v0 = acc[mi][ni][0] * alpha;
            float v1 = acc[mi][ni][1] * alpha;
            float v2 = acc[mi][ni][2] * alpha;
            float v3 = acc[mi][ni][3] * alpha;
            if (OUT_HALF) {
                __half* Ch = (__half*)Cv + (long long)blockIdx.z * sC;
                *reinterpret_cast<__half2*>(&Ch[(long long)row * ldc + col]) =
                    __floats2half2_rn(v0, v1);
                *reinterpret_cast<__half2*>(&Ch[(long long)(row + 8) * ldc + col]) =
                    __floats2half2_rn(v2, v3);
            } else {
                float* Cf = (float*)Cv + (long long)blockIdx.z * sC;
                *reinterpret_cast<float2*>(&Cf[(long long)row * ldc + col])       = make_float2(v0, v1);
                *reinterpret_cast<float2*>(&Cf[(long long)(row + 8) * ldc + col]) = make_float2(v2, v3);
            }
        }
    }
}

// ---------------- fp32 -> fp16 conversion ----------------
__global__ __launch_bounds__(256)
void f2h_k(const float* __restrict__ in, __half* __restrict__ out, int n4)
{
    int i = blockIdx.x * blockDim.x + threadIdx.x;
    if (i < n4) {
        float4 v = reinterpret_cast<const float4*>(in)[i];
        __half2* o = reinterpret_cast<__half2*>(out);
        o[2 * i + 0] = __floats2half2_rn(v.x, v.y);
        o[2 * i + 1] = __floats2half2_rn(v.z, v.w);
    }
}

// ---------------- softmax: fp32 score row -> fp16 prob row ----------------
__global__ __launch_bounds__(256)
void softmax_rows(const float* __restrict__ S, __half* __restrict__ P)
{
    const long long row = blockIdx.x;
    const float4* p = reinterpret_cast<const float4*>(S + row * 4096);
    __half2* ph = reinterpret_cast<__half2*>(P + row * 4096);
    const int tid = threadIdx.x;
    __shared__ float red[8];

    float4 v[4];
    float mx = -1e30f;
    #pragma unroll
    for (int i = 0; i < 4; i++) {
        v[i] = p[tid + 256 * i];
        mx = fmaxf(mx, fmaxf(fmaxf(v[i].x, v[i].y), fmaxf(v[i].z, v[i].w)));
    }
    #pragma unroll
    for (int o = 16; o > 0; o >>= 1) mx = fmaxf(mx, __shfl_xor_sync(0xffffffffu, mx, o));
    if ((tid & 31) == 0) red[tid >> 5] = mx;
    __syncthreads();
    if (tid < 32) {
        float m = (tid < 8) ? red[tid] : -1e30f;
        #pragma unroll
        for (int o = 4; o > 0; o >>= 1) m = fmaxf(m, __shfl_xor_sync(0xffffffffu, m, o));
        if (tid == 0) red[0] = m;
    }
    __syncthreads();
    mx = red[0];
    __syncthreads();

    float sum = 0.0f;
    #pragma unroll
    for (int i = 0; i < 4; i++) {
        v[i].x = __expf(v[i].x - mx);
        v[i].y = __expf(v[i].y - mx);
        v[i].z = __expf(v[i].z - mx);
        v[i].w = __expf(v[i].w - mx);
        sum += v[i].x + v[i].y + v[i].z + v[i].w;
    }
    #pragma unroll
    for (int o = 16; o > 0; o >>= 1) sum += __shfl_xor_sync(0xffffffffu, sum, o);
    if ((tid & 31) == 0) red[tid >> 5] = sum;
    __syncthreads();
    if (tid < 32) {
        float s = (tid < 8) ? red[tid] : 0.0f;
        #pragma unroll
        for (int o = 4; o > 0; o >>= 1) s += __shfl_xor_sync(0xffffffffu, s, o);
        if (tid == 0) red[0] = s;
    }
    __syncthreads();
    const float inv = 1.0f / red[0];

    #pragma unroll
    for (int i = 0; i < 4; i++) {
        int idx = tid + 256 * i;
        ph[2 * idx + 0] = __floats2half2_rn(v[i].x * inv, v[i].y * inv);
        ph[2 * idx + 1] = __floats2half2_rn(v[i].z * inv, v[i].w * inv);
    }
}

// ---------------- launch ----------------
extern "C" void kernel_launch(void* const* d_in, const int* in_sizes, int n_in,
                              void* d_out, int out_size)
{
    const float* x  = (const float*)d_in[0];
    const float* Wq = (const float*)d_in[1];
    const float* Wk = (const float*)d_in[2];
    const float* Wv = (const float*)d_in[3];
    float* out = (float*)d_out;

    __half *Xh, *Wh, *Q, *Kp, *Vt, *P;
    float *S;
    cudaGetSymbolAddress((void**)&Xh, g_Xh);
    cudaGetSymbolAddress((void**)&Wh, g_Wh);
    cudaGetSymbolAddress((void**)&Q,  g_Q);
    cudaGetSymbolAddress((void**)&Kp, g_K);
    cudaGetSymbolAddress((void**)&Vt, g_Vt);
    cudaGetSymbolAddress((void**)&S,  g_S);
    cudaGetSymbolAddress((void**)&P,  g_P);

    const size_t shmem = (size_t)2 * (BM + BN) * PAD * 4;  // 81920
    cudaFuncSetAttribute(gemm_h<true>,  cudaFuncAttributeMaxDynamicSharedMemorySize, (int)shmem);
    cudaFuncSetAttribute(gemm_h<false>, cudaFuncAttributeMaxDynamicSharedMemorySize, (int)shmem);

    const long long BS  = (long long)SEQ * DIM;
    const long long BSS = (long long)SEQ * SEQ;
    const int WN = DIM * DIM;
    dim3 blk(256);

    // inputs -> fp16
    f2h_k<<<(BATCH * SEQ * DIM / 4 + 255) / 256, blk>>>(x,  Xh,           BATCH * SEQ * DIM / 4);
    f2h_k<<<(WN / 4 + 255) / 256, blk>>>(Wq, Wh + 0LL * WN, WN / 4);
    f2h_k<<<(WN / 4 + 255) / 256, blk>>>(Wk, Wh + 1LL * WN, WN / 4);
    f2h_k<<<(WN / 4 + 255) / 256, blk>>>(Wv, Wh + 2LL * WN, WN / 4);

    // Q = X @ Wq^T ; K = X @ Wk^T   (M spans all batches), fp16 outputs
    gemm_h<true><<<dim3(DIM / BN, BATCH * SEQ / BM, 1), blk, shmem>>>(
        Xh, Wh + 0LL * WN, Q, BATCH * SEQ, DIM, DIM, DIM, DIM, DIM, 0, 0, 0, 1.0f);
    gemm_h<true><<<dim3(DIM / BN, BATCH * SEQ / BM, 1), blk, shmem>>>(
        Xh, Wh + 1LL * WN, Kp, BATCH * SEQ, DIM, DIM, DIM, DIM, DIM, 0, 0, 0, 1.0f);

    // Vt[b] = Wv @ X_b^T  -> [D][S], coalesced stores
    gemm_h<true><<<dim3(SEQ / BN, DIM / BM, BATCH), blk, shmem>>>(
        Wh + 2LL * WN, Xh, Vt, DIM, SEQ, DIM, DIM, DIM, SEQ, 0, BS, BS, 1.0f);

    // S[b] = (Q_b @ K_b^T) / 32   (fp32 scores)
    gemm_h<false><<<dim3(SEQ / BN, SEQ / BM, BATCH), blk, shmem>>>(
        Q, Kp, S, SEQ, SEQ, DIM, DIM, DIM, SEQ, BS, BS, BSS, 0.03125f);

    // P = softmax(S) rows, fp16
    softmax_rows<<<BATCH * SEQ, blk>>>(S, P);

    // out[b] = P_b @ V_b   (B = Vt_b is [D][S], N-major; fp32 out)
    gemm_h<false><<<dim3(DIM / BN, SEQ / BM, BATCH), blk, shmem>>>(
        P, Vt, out, SEQ, DIM, SEQ, SEQ, SEQ, DIM, BSS, BS, BS, 1.0f);
}

// round 17
// speedup vs baseline: 1.0676x; 1.0676x over previous
#include <cuda_runtime.h>
#include <cuda_fp16.h>
#include <cstdint>

// ---------------------------------------------------------------------------
// SelfAttention: out = softmax((x@Wq^T)(x@Wk^T)^T / sqrt(D)) @ (x@Wv^T)
// B=4, S=4096, D=1024.  fp16 tensor GEMMs (m16n8k16, fp32 accum).
// GEMM inner loop BYTE-IDENTICAL to R9 (best: 1355us; R10/12/13 showed it
// is a local optimum).  Banked safe deltas only:
//  - Vt = Wv @ X^T (coalesced half2 stores; kills R9's scatter epilogue)
//  - merged Q||K projection (one GEMM, N=2048; Wq/Wk adjacent in g_Wh)
//  - QK^T alpha pre-multiplied by log2e; softmax uses ex2.approx.ftz.f32
// (Resubmit of R14: R16 "container failed twice" was infra flake — this
//  kernel uses only instruction classes proven to run in R9/R12/R13.)
// ---------------------------------------------------------------------------

#define BM 128
#define BN 128
#define BKH 64   // k halves per tile = 32 words
#define PAD 36   // smem row stride in words (144 B), conflict-free

static const int BATCH = 4;
static const int SEQ   = 4096;
static const int DIM   = 1024;

// Scratch (device globals: allocation-free rule)
__device__ __half g_Xh[4LL * 4096 * 1024];   // fp16 x
__device__ __half g_Wh[3LL * 1024 * 1024];   // fp16 Wq|Wk|Wv (adjacent)
__device__ __half g_QK[4LL * 4096 * 2048];   // Q||K interleaved, ld=2048
__device__ __half g_Vt[4LL * 1024 * 4096];   // per batch: [D][S]
__device__ float  g_S [4LL * 4096 * 4096];   // scores * log2e/32
__device__ __half g_P [4LL * 4096 * 4096];   // probabilities

__device__ __forceinline__ float ex2f(float x) {
    float r; asm("ex2.approx.ftz.f32 %0, %1;" : "=f"(r) : "f"(x));
    return r;
}

__device__ __forceinline__ void mma_f16(float c[4],
                                        uint32_t a0, uint32_t a1, uint32_t a2, uint32_t a3,
                                        uint32_t b0, uint32_t b1) {
    asm volatile(
        "mma.sync.aligned.m16n8k16.row.col.f32.f16.f16.f32 "
        "{%0,%1,%2,%3}, {%4,%5,%6,%7}, {%8,%9}, {%0,%1,%2,%3};\n"
        : "+f"(c[0]), "+f"(c[1]), "+f"(c[2]), "+f"(c[3])
        : "r"(a0), "r"(a1), "r"(a2), "r"(a3), "r"(b0), "r"(b1));
}

// C[M,N] = alpha * A[M,K] @ B[N,K]^T  (fp16 in, fp32 accum; B stored N-major)
// OUT_HALF: C is __half else float.  Batched via blockIdx.z.
template <bool OUT_HALF>
__global__ __launch_bounds__(256, 1)
void gemm_h(const __half* __restrict__ A, const __half* __restrict__ B,
            void* __restrict__ Cv,
            int M, int N, int K, int lda, int ldb, int ldc,
            long long sA, long long sB, long long sC, float alpha)
{
    extern __shared__ uint32_t smem[];
    uint32_t* AsBase = smem;                   // [2][BM][PAD] words
    uint32_t* BsBase = smem + 2 * BM * PAD;    // [2][BN][PAD] words

    A += (long long)blockIdx.z * sA;
    B += (long long)blockIdx.z * sB;

    const int m0 = blockIdx.y * BM;
    const int n0 = blockIdx.x * BN;

    const int tid  = threadIdx.x;
    const int lane = tid & 31;
    const int wid  = tid >> 5;
    const int wm   = wid & 1;   // warp row (0..1), 64 rows each
    const int wn   = wid >> 1;  // warp col (0..3), 32 cols each
    const int g    = lane >> 2; // 0..7
    const int tg   = lane & 3;  // 0..3

    // global->reg staging: 256 threads cover 32 rows x 32 words / pass
    const int lrow = tid >> 3;        // 0..31
    const int lc   = tid & 7;         // chunk (4 words = 8 halves)

    uint4 ra[4], rb[4];

    auto ldg_tile = [&](int k0) {
        #pragma unroll
        for (int i = 0; i < 4; i++) {
            int r = lrow + 32 * i;
            ra[i] = *reinterpret_cast<const uint4*>(&A[(long long)(m0 + r) * lda + k0 + lc * 8]);
            rb[i] = *reinterpret_cast<const uint4*>(&B[(long long)(n0 + r) * ldb + k0 + lc * 8]);
        }
    };
    auto sts_tile = [&](int st) {
        uint32_t* as = AsBase + st * BM * PAD;
        uint32_t* bs = BsBase + st * BN * PAD;
        #pragma unroll
        for (int i = 0; i < 4; i++) {
            int r = lrow + 32 * i;
            *reinterpret_cast<uint4*>(&as[r * PAD + lc * 4]) = ra[i];
            *reinterpret_cast<uint4*>(&bs[r * PAD + lc * 4]) = rb[i];
        }
    };

    float acc[4][4][4];
    #pragma unroll
    for (int mi = 0; mi < 4; mi++)
        #pragma unroll
        for (int ni = 0; ni < 4; ni++)
            #pragma unroll
            for (int j = 0; j < 4; j++) acc[mi][ni][j] = 0.0f;

    ldg_tile(0);
    sts_tile(0);
    __syncthreads();

    const int ntiles = K / BKH;
    for (int kt = 0; kt < ntiles; kt++) {
        const int st = kt & 1;
        if (kt + 1 < ntiles) ldg_tile((kt + 1) * BKH);

        const uint32_t* as = AsBase + st * BM * PAD;
        const uint32_t* bs = BsBase + st * BN * PAD;

        #pragma unroll
        for (int kk = 0; kk < 4; kk++) {       // four k16 steps per 64-half tile
            const int kb = kk * 8;             // word offset
            uint32_t af[4][4], bf[4][2];
            #pragma unroll
            for (int mi = 0; mi < 4; mi++) {
                int row = wm * 64 + mi * 16 + g;
                af[mi][0] = as[row * PAD + kb + tg];
                af[mi][1] = as[(row + 8) * PAD + kb + tg];
                af[mi][2] = as[row * PAD + kb + tg + 4];
                af[mi][3] = as[(row + 8) * PAD + kb + tg + 4];
            }
            #pragma unroll
            for (int ni = 0; ni < 4; ni++) {
                int col = wn * 32 + ni * 8 + g;
                bf[ni][0] = bs[col * PAD + kb + tg];
                bf[ni][1] = bs[col * PAD + kb + tg + 4];
            }
            #pragma unroll
            for (int mi = 0; mi < 4; mi++)
                #pragma unroll
                for (int ni = 0; ni < 4; ni++)
                    mma_f16(acc[mi][ni], af[mi][0], af[mi][1], af[mi][2], af[mi][3],
                            bf[ni][0], bf[ni][1]);
        }

        if (kt + 1 < ntiles) sts_tile((kt + 1) & 1);
        __syncthreads();
    }

    // epilogue: c0:(g,2tg) c1:(g,2tg+1) c2:(g+8,2tg) c3:(g+8,2tg+1)
    #pragma unroll
    for (int mi = 0; mi < 4; mi++) {
        #pragma unroll
        for (int ni = 0; ni < 4; ni++) {
            int row = m0 + wm * 64 + mi * 16 + g;
            int col = n0 + wn * 32 + ni * 8 + 2 * tg;
            float v0 = acc[mi][ni][0] * alpha;
            float v1 = acc[mi][ni][1] * alpha;
            float v2 = acc[mi][ni][2] * alpha;
            float v3 = acc[mi][ni][3] * alpha;
            if (OUT_HALF) {
                __half* Ch = (__half*)Cv + (long long)blockIdx.z * sC;
                *reinterpret_cast<__half2*>(&Ch[(long long)row * ldc + col]) =
                    __floats2half2_rn(v0, v1);
                *reinterpret_cast<__half2*>(&Ch[(long long)(row + 8) * ldc + col]) =
                    __floats2half2_rn(v2, v3);
            } else {
                float* Cf = (float*)Cv + (long long)blockIdx.z * sC;
                *reinterpret_cast<float2*>(&Cf[(long long)row * ldc + col])       = make_float2(v0, v1);
                *reinterpret_cast<float2*>(&Cf[(long long)(row + 8) * ldc + col]) = make_float2(v2, v3);
            }
        }
    }
}

// ---------------- fp32 -> fp16 conversion ----------------
__global__ __launch_bounds__(256)
void f2h_k(const float* __restrict__ in, __half* __restrict__ out, int n4)
{
    int i = blockIdx.x * blockDim.x + threadIdx.x;
    if (i < n4) {
        float4 v = reinterpret_cast<const float4*>(in)[i];
        __half2* o = reinterpret_cast<__half2*>(out);
        o[2 * i + 0] = __floats2half2_rn(v.x, v.y);
        o[2 * i + 1] = __floats2half2_rn(v.z, v.w);
    }
}

// ---- softmax: row of S (pre-scaled by log2e/32) -> fp16 prob row (base-2) --
__global__ __launch_bounds__(256)
void softmax_rows(const float* __restrict__ S, __half* __restrict__ P)
{
    const long long row = blockIdx.x;
    const float4* p = reinterpret_cast<const float4*>(S + row * 4096);
    __half2* ph = reinterpret_cast<__half2*>(P + row * 4096);
    const int tid = threadIdx.x;
    __shared__ float red[8];

    float4 v[4];
    float mx = -1e30f;
    #pragma unroll
    for (int i = 0; i < 4; i++) {
        v[i] = p[tid + 256 * i];
        mx = fmaxf(mx, fmaxf(fmaxf(v[i].x, v[i].y), fmaxf(v[i].z, v[i].w)));
    }
    #pragma unroll
    for (int o = 16; o > 0; o >>= 1) mx = fmaxf(mx, __shfl_xor_sync(0xffffffffu, mx, o));
    if ((tid & 31) == 0) red[tid >> 5] = mx;
    __syncthreads();
    if (tid < 32) {
        float m = (tid < 8) ? red[tid] : -1e30f;
        #pragma unroll
        for (int o = 4; o > 0; o >>= 1) m = fmaxf(m, __shfl_xor_sync(0xffffffffu, m, o));
        if (tid == 0) red[0] = m;
    }
    __syncthreads();
    mx = red[0];
    __syncthreads();

    float sum = 0.0f;
    #pragma unroll
    for (int i = 0; i < 4; i++) {
        v[i].x = ex2f(v[i].x - mx);     // exp2 of log2-scaled scores == exp
        v[i].y = ex2f(v[i].y - mx);
        v[i].z = ex2f(v[i].z - mx);
        v[i].w = ex2f(v[i].w - mx);
        sum += v[i].x + v[i].y + v[i].z + v[i].w;
    }
    #pragma unroll
    for (int o = 16; o > 0; o >>= 1) sum += __shfl_xor_sync(0xffffffffu, sum, o);
    if ((tid & 31) == 0) red[tid >> 5] = sum;
    __syncthreads();
    if (tid < 32) {
        float s = (tid < 8) ? red[tid] : 0.0f;
        #pragma unroll
        for (int o = 4; o > 0; o >>= 1) s += __shfl_xor_sync(0xffffffffu, s, o);
        if (tid == 0) red[0] = s;
    }
    __syncthreads();
    const float inv = 1.0f / red[0];

    #pragma unroll
    for (int i = 0; i < 4; i++) {
        int idx = tid + 256 * i;
        ph[2 * idx + 0] = __floats2half2_rn(v[i].x * inv, v[i].y * inv);
        ph[2 * idx + 1] = __floats2half2_rn(v[i].z * inv, v[i].w * inv);
    }
}

// ---------------- launch ----------------
extern "C" void kernel_launch(void* const* d_in, const int* in_sizes, int n_in,
                              void* d_out, int out_size)
{
    const float* x  = (const float*)d_in[0];
    const float* Wq = (const float*)d_in[1];
    const float* Wk = (const float*)d_in[2];
    const float* Wv = (const float*)d_in[3];
    float* out = (float*)d_out;

    __half *Xh, *Wh, *QK, *Vt, *P;
    float *S;
    cudaGetSymbolAddress((void**)&Xh, g_Xh);
    cudaGetSymbolAddress((void**)&Wh, g_Wh);
    cudaGetSymbolAddress((void**)&QK, g_QK);
    cudaGetSymbolAddress((void**)&Vt, g_Vt);
    cudaGetSymbolAddress((void**)&S,  g_S);
    cudaGetSymbolAddress((void**)&P,  g_P);

    const size_t shmem = (size_t)2 * (BM + BN) * PAD * 4; // 73728
    cudaFuncSetAttribute(gemm_h<true>,  cudaFuncAttributeMaxDynamicSharedMemorySize, (int)shmem);
    cudaFuncSetAttribute(gemm_h<false>, cudaFuncAttributeMaxDynamicSharedMemorySize, (int)shmem);

    const long long BS   = (long long)SEQ * DIM;     // 4M elems / batch
    const long long BS2  = (long long)SEQ * 2048;    // QK buffer stride / batch
    const long long BSS  = (long long)SEQ * SEQ;
    const int WN = DIM * DIM;
    dim3 blk(256);

    // inputs -> fp16
    f2h_k<<<(BATCH * SEQ * DIM / 4 + 255) / 256, blk>>>(x,  Xh,           BATCH * SEQ * DIM / 4);
    f2h_k<<<(WN / 4 + 255) / 256, blk>>>(Wq, Wh + 0LL * WN, WN / 4);
    f2h_k<<<(WN / 4 + 255) / 256, blk>>>(Wk, Wh + 1LL * WN, WN / 4);
    f2h_k<<<(WN / 4 + 255) / 256, blk>>>(Wv, Wh + 2LL * WN, WN / 4);

    // QK = X @ [Wq;Wk]^T  (N=2048: cols 0..1023 = Q, 1024..2047 = K)
    gemm_h<true><<<dim3(2048 / BN, BATCH * SEQ / BM, 1), blk, shmem>>>(
        Xh, Wh, QK, BATCH * SEQ, 2048, DIM, DIM, DIM, 2048, 0, 0, 0, 1.0f);

    // Vt[b] = Wv @ X_b^T  -> [D][S], coalesced half2 stores
    gemm_h<true><<<dim3(SEQ / BN, DIM / BM, BATCH), blk, shmem>>>(
        Wh + 2LL * WN, Xh, Vt, DIM, SEQ, DIM, DIM, DIM, SEQ, 0, BS, BS, 1.0f);

    // S[b] = (Q_b @ K_b^T) * log2e/32   (fp32, base-2-ready scores)
    gemm_h<false><<<dim3(SEQ / BN, SEQ / BM, BATCH), blk, shmem>>>(
        QK, QK + 1024, S, SEQ, SEQ, DIM, 2048, 2048, SEQ, BS2, BS2, BSS,
        1.4426950408889634f / 32.0f);

    // P = softmax rows (exp2 of pre-scaled scores), fp16
    softmax_rows<<<BATCH * SEQ, blk>>>(S, P);

    // out[b] = P_b @ V_b   (B = Vt_b is [D][S], N-major; fp32 out)
    gemm_h<false><<<dim3(DIM / BN, SEQ / BM, BATCH), blk, shmem>>>(
        P, Vt, out, SEQ, DIM, SEQ, SEQ, SEQ, DIM, BSS, BS, BS, 1.0f);
}